// round 4
// baseline (speedup 1.0000x reference)
#include <cuda_runtime.h>
#include <math.h>

// PointNetKAN on GB300, round 4: 3xTF32 error-compensated tensor-core GEMM.
//  - a = a_hi + a_lo (tf32 split); acc += a_hi*b_hi + a_hi*b_lo + a_lo*b_hi (fp32)
//  - interleaved hi/lo smem layout: one LDS.128 per fragment (hi+lo)
//  - tanh+BN hoisted per layer; fused stats (+max) epilogue; P0 + gf folded to biases

#define NPTS 32768
#define EPSV 1e-5f

typedef unsigned long long u64;
typedef unsigned int u32;

// ---------------- scratch ----------------
__device__ __align__(16) float g_bufA[32u * 1024u * 1024u];
__device__ __align__(16) float g_bufB[32u * 512u * 1024u];
__device__ __align__(16) float g_bufT[32u * 512u * 1024u];   // tanh'd layer input
__device__ __align__(16) float g_y2[32u * 64u * 1024u];      // raw L2 out
__device__ __align__(16) float g_t2[32u * 64u * 1024u];      // tanh(bn(y2)) reused by L3, L6
__device__ double g_dsum[10 * 1024];
__device__ double g_dss[10 * 1024];
__device__ u32 g_maxkey[32 * 1024];
__device__ __align__(16) float g_gpoly[32 * 1024 * 4];
__device__ float g_bias6[32 * 512];
__device__ float g_cbias[9 * 1024];

// ---------------- helpers ----------------
__device__ __forceinline__ u32 tf32of(float f) {
    u32 r; asm("cvt.rna.tf32.f32 %0, %1;" : "=r"(r) : "f"(f)); return r;
}
__device__ __forceinline__ void tf32split(float f, u32& hi, u32& lo) {
    hi = tf32of(f);
    lo = tf32of(f - __uint_as_float(hi));
}
__device__ __forceinline__ u32 fkey(float f) {
    u32 u = __float_as_uint(f);
    return (u & 0x80000000u) ? ~u : (u | 0x80000000u);
}
__device__ __forceinline__ float finv(u32 k) {
    u32 u = (k & 0x80000000u) ? (k ^ 0x80000000u) : ~k;
    return __uint_as_float(u);
}
__device__ __forceinline__ float ftanh(float x) {
    float ax = fminf(fabsf(x), 15.0f);
    float e = __expf(2.0f * ax);
    float t = __fdividef(e - 1.0f, e + 1.0f);
    return copysignf(t, x);
}
__device__ __forceinline__ void jacobi3(float t, float& p1, float& p2, float& p3) {
    p1 = 2.0f * t;
    p2 = 3.75f * t * t - 0.75f;
    p3 = (56.0f / 30.0f) * t * p2 - 0.8f * p1;
}
// interleaved hi/lo position: per 8-k group of 16 u32: [hi(k),hi(k+4),lo(k),lo(k+4)] per quad
__device__ __forceinline__ int kpos_hi(int k) {
    return ((k >> 3) << 4) + ((k & 3) << 2) + ((k >> 2) & 1);
}
__device__ __forceinline__ void mma_tf32(float* c, u32 a0, u32 a1, u32 a2, u32 a3,
                                         u32 b0, u32 b1) {
    asm("mma.sync.aligned.m16n8k8.row.col.f32.tf32.tf32.f32 "
        "{%0,%1,%2,%3}, {%4,%5,%6,%7}, {%8,%9}, {%0,%1,%2,%3};"
        : "+f"(c[0]), "+f"(c[1]), "+f"(c[2]), "+f"(c[3])
        : "r"(a0), "r"(a1), "r"(a2), "r"(a3), "r"(b0), "r"(b1));
}

// ---------------- 3xTF32 tensor-core KAN GEMM ----------------
// T:   (32, CIN, 1024) pre-tanh'd input
// w:   (CIN_total, COUT, 4); poly rows 1..3 enter the GEMM
// out: (32, COUT, 1024) raw; per-channel stats (+max) via atomics
template <int CIN, int COUT, int TO, bool DOMAX>
__global__ __launch_bounds__(256) void kan_tc(
    const float* __restrict__ T, const float* __restrict__ w,
    const float* __restrict__ cbias, const float* __restrict__ bias,
    float* __restrict__ out, double* __restrict__ dsum,
    double* __restrict__ dss, u32* __restrict__ maxkey) {
    constexpr int KC = (CIN < 8) ? CIN : 8;  // channels per chunk
    constexpr int KR = 3 * KC;               // poly rows per chunk
    constexpr int KR8 = (KR + 7) & ~7;
    constexpr int KS = KR8 / 8;              // mma k-steps per chunk
    constexpr int STR = 48;                  // u32 per smem row (2 * 24, 48 mod 32 == 16)
    constexpr int WN = TO / 4;               // warp n-extent
    constexpr int NT = WN / 8;               // n8 tiles per warp

    __shared__ __align__(16) u32 As[128 * STR];
    __shared__ __align__(16) u32 Bs[TO * STR];

    const int tid = threadIdx.x;
    const int lane = tid & 31, wid = tid >> 5;
    const int g = lane >> 2, tg = lane & 3;
    const int wm = wid & 1, wn = wid >> 1;
    const int bx = blockIdx.x;
    const int b = bx >> 3;
    const int n0 = (bx & 7) * 128;
    const int o0 = blockIdx.y * TO;

    float acc[4][NT][4];
#pragma unroll
    for (int mt = 0; mt < 4; mt++)
#pragma unroll
        for (int nt = 0; nt < NT; nt++)
#pragma unroll
            for (int r = 0; r < 4; r++) acc[mt][nt][r] = 0.0f;

    for (int ck = 0; ck < CIN / KC; ck++) {
        const int c0 = ck * KC;
        // A: t -> 3 Jacobi rows, tf32 hi/lo
#pragma unroll
        for (int e = tid; e < KC * 128; e += 256) {
            int c = e >> 7, p = e & 127;
            float t = T[((size_t)(b * CIN + c0 + c)) * 1024 + n0 + p];
            float p1, p2, p3;
            jacobi3(t, p1, p2, p3);
            int kb = 3 * c;
            u32* row = As + p * STR;
            u32 hi, lo;
            tf32split(p1, hi, lo); int q = kpos_hi(kb + 0); row[q] = hi; row[q + 2] = lo;
            tf32split(p2, hi, lo); q = kpos_hi(kb + 1); row[q] = hi; row[q + 2] = lo;
            tf32split(p3, hi, lo); q = kpos_hi(kb + 2); row[q] = hi; row[q + 2] = lo;
        }
        // B: weight rows 1..3, tf32 hi/lo
#pragma unroll
        for (int e = tid; e < KC * TO; e += 256) {
            int c = e / TO, o = e - c * TO;
            const float4 w4 = *(const float4*)&w[(((size_t)(c0 + c)) * COUT + o0 + o) * 4];
            int kb = 3 * c;
            u32* row = Bs + o * STR;
            u32 hi, lo;
            tf32split(w4.y, hi, lo); int q = kpos_hi(kb + 0); row[q] = hi; row[q + 2] = lo;
            tf32split(w4.z, hi, lo); q = kpos_hi(kb + 1); row[q] = hi; row[q + 2] = lo;
            tf32split(w4.w, hi, lo); q = kpos_hi(kb + 2); row[q] = hi; row[q + 2] = lo;
        }
        if (KR8 != KR) {  // zero logical k = 6,7 (CIN=2 case): u32 slots 9,11,13,15
            for (int e = tid; e < 128; e += 256) {
                u32* row = As + e * STR;
                row[9] = 0u; row[11] = 0u; row[13] = 0u; row[15] = 0u;
            }
            for (int e = tid; e < TO; e += 256) {
                u32* row = Bs + e * STR;
                row[9] = 0u; row[11] = 0u; row[13] = 0u; row[15] = 0u;
            }
        }
        __syncthreads();

        const u32* ap = As + (wm * 64 + g) * STR + tg * 4;
        const u32* bp = Bs + (wn * WN + g) * STR + tg * 4;
#pragma unroll
        for (int ks = 0; ks < KS; ks++) {
            uint4 a0[4], a1[4];
#pragma unroll
            for (int mt = 0; mt < 4; mt++) {
                a0[mt] = *(const uint4*)(ap + mt * 16 * STR + ks * 16);
                a1[mt] = *(const uint4*)(ap + (mt * 16 + 8) * STR + ks * 16);
            }
            uint4 bf[NT];
#pragma unroll
            for (int nt = 0; nt < NT; nt++)
                bf[nt] = *(const uint4*)(bp + nt * 8 * STR + ks * 16);
#pragma unroll
            for (int mt = 0; mt < 4; mt++)
#pragma unroll
                for (int nt = 0; nt < NT; nt++) {
                    // hi*hi
                    mma_tf32(acc[mt][nt], a0[mt].x, a1[mt].x, a0[mt].y, a1[mt].y,
                             bf[nt].x, bf[nt].y);
                    // hi*lo
                    mma_tf32(acc[mt][nt], a0[mt].x, a1[mt].x, a0[mt].y, a1[mt].y,
                             bf[nt].z, bf[nt].w);
                    // lo*hi
                    mma_tf32(acc[mt][nt], a0[mt].z, a1[mt].z, a0[mt].w, a1[mt].w,
                             bf[nt].x, bf[nt].y);
                }
        }
        __syncthreads();
    }

    // epilogue: bias, stores, fused stats
#pragma unroll
    for (int nt = 0; nt < NT; nt++) {
        const int o = o0 + wn * WN + nt * 8 + 2 * tg;
        float add0 = cbias[o] + (bias ? bias[b * COUT + o] : 0.0f);
        float add1 = cbias[o + 1] + (bias ? bias[b * COUT + o + 1] : 0.0f);
        float s0 = 0, ss0 = 0, s1 = 0, ss1 = 0;
        float mx0 = -3.4e38f, mx1 = -3.4e38f;
#pragma unroll
        for (int mt = 0; mt < 4; mt++) {
            int pt = n0 + wm * 64 + mt * 16 + g;
            float v00 = acc[mt][nt][0] + add0, v01 = acc[mt][nt][1] + add1;
            float v10 = acc[mt][nt][2] + add0, v11 = acc[mt][nt][3] + add1;
            float* r0 = out + ((size_t)(b * COUT + o)) * 1024 + pt;
            float* r1 = out + ((size_t)(b * COUT + o + 1)) * 1024 + pt;
            r0[0] = v00; r0[8] = v10; r1[0] = v01; r1[8] = v11;
            s0 += v00 + v10; ss0 += v00 * v00 + v10 * v10;
            s1 += v01 + v11; ss1 += v01 * v01 + v11 * v11;
            if (DOMAX) { mx0 = fmaxf(mx0, fmaxf(v00, v10)); mx1 = fmaxf(mx1, fmaxf(v01, v11)); }
        }
#pragma unroll
        for (int off = 4; off < 32; off <<= 1) {
            s0 += __shfl_xor_sync(0xffffffffu, s0, off);
            ss0 += __shfl_xor_sync(0xffffffffu, ss0, off);
            s1 += __shfl_xor_sync(0xffffffffu, s1, off);
            ss1 += __shfl_xor_sync(0xffffffffu, ss1, off);
            if (DOMAX) {
                mx0 = fmaxf(mx0, __shfl_xor_sync(0xffffffffu, mx0, off));
                mx1 = fmaxf(mx1, __shfl_xor_sync(0xffffffffu, mx1, off));
            }
        }
        if (lane < 4) {
            atomicAdd(&dsum[o], (double)s0);
            atomicAdd(&dss[o], (double)ss0);
            atomicAdd(&dsum[o + 1], (double)s1);
            atomicAdd(&dss[o + 1], (double)ss1);
            if (DOMAX) {
                atomicMax(&maxkey[b * 1024 + o], fkey(mx0));
                atomicMax(&maxkey[b * 1024 + o + 1], fkey(mx1));
            }
        }
    }
}

// ---------------- BN (from raw accumulators) + fast tanh ----------------
__global__ void tanh_bn_kernel(const float* __restrict__ in, const double* __restrict__ dsum,
                               const double* __restrict__ dss, int C, float* __restrict__ out) {
    int c = blockIdx.x % C;
    float m = 0.0f, r = 1.0f;
    if (dsum) {
        double mm = dsum[c] * (1.0 / NPTS);
        double var = fma(-mm, mm, dss[c] * (1.0 / NPTS));
        m = (float)mm;
        r = rsqrtf((float)var + EPSV);
    }
    const float4* ip = (const float4*)(in + (size_t)blockIdx.x * 1024);
    float4 v = ip[threadIdx.x];
    v.x = ftanh((v.x - m) * r);
    v.y = ftanh((v.y - m) * r);
    v.z = ftanh((v.z - m) * r);
    v.w = ftanh((v.w - m) * r);
    ((float4*)(out + (size_t)blockIdx.x * 1024))[threadIdx.x] = v;
}

// ---------------- all per-layer P0 constant biases, one launch ----------------
struct CBArgs { const float* w[9]; int cin[9]; int cout[9]; };
__global__ void cbias_all_kernel(CBArgs a, float* __restrict__ cb) {
    int l = blockIdx.y;
    int o = blockIdx.x * 256 + threadIdx.x;
    if (o >= a.cout[l]) return;
    const float* w = a.w[l];
    int CO = a.cout[l];
    float s = 0.0f;
    for (int c = 0; c < a.cin[l]; c++) s += w[((size_t)c * CO + o) * 4];
    cb[l * 1024 + o] = s;
}

// ---------------- polys of normalized global feature ----------------
__global__ void gpoly_kernel(const u32* __restrict__ mk, const double* __restrict__ dsum,
                             const double* __restrict__ dss, float* __restrict__ gp) {
    int i = blockIdx.x * 256 + threadIdx.x;  // b*1024 + c
    int c = i & 1023;
    double mm = dsum[c] * (1.0 / NPTS);
    double var = fma(-mm, mm, dss[c] * (1.0 / NPTS));
    float r = rsqrtf((float)var + EPSV);
    float t = ftanh((finv(mk[i]) - (float)mm) * r);
    float p1, p2, p3;
    jacobi3(t, p1, p2, p3);
    ((float4*)gp)[i] = make_float4(1.0f, p1, p2, p3);
}

// ---------------- layer-6 bias from gf rows of w6 ----------------
__global__ void bias6_kernel(const float* __restrict__ gp, const float* __restrict__ w6g,
                             float* __restrict__ bias) {
    int b = blockIdx.x;
    int o = blockIdx.y * 64 + (threadIdx.x & 63);
    int js = threadIdx.x >> 6;
    const float4* g4 = (const float4*)(gp + (size_t)b * 4096);
    float acc = 0.0f;
    for (int j = js * 256; j < js * 256 + 256; j++) {
        float4 g = g4[j];
        float4 wv = *(const float4*)&w6g[((size_t)j * 512 + o) * 4];
        acc += g.x * wv.x + g.y * wv.y + g.z * wv.z + g.w * wv.w;
    }
    __shared__ float sh[256];
    sh[threadIdx.x] = acc;
    __syncthreads();
    if (threadIdx.x < 64)
        bias[b * 512 + o] = sh[threadIdx.x] + sh[threadIdx.x + 64] +
                            sh[threadIdx.x + 128] + sh[threadIdx.x + 192];
}

// ---------------- final layer: 128 -> 3 (reads pre-tanh'd input) ----------------
__global__ void final_kernel(const float* __restrict__ tin, const float* __restrict__ w,
                             float* __restrict__ out) {
    __shared__ float ws[128 * 12];
    for (int e = threadIdx.x; e < 1536; e += 256) ws[e] = w[e];
    __syncthreads();
    int gidx = blockIdx.x * 256 + threadIdx.x;
    int b = gidx >> 10, n = gidx & 1023;
    float a0 = 0.0f, a1 = 0.0f, a2 = 0.0f;
    for (int c = 0; c < 128; c++) {
        float t = tin[((size_t)(b * 128 + c)) * 1024 + n];
        float p1, p2, p3;
        jacobi3(t, p1, p2, p3);
        const float* wc = &ws[c * 12];
        a0 += wc[0] + p1 * wc[1] + p2 * wc[2] + p3 * wc[3];
        a1 += wc[4] + p1 * wc[5] + p2 * wc[6] + p3 * wc[7];
        a2 += wc[8] + p1 * wc[9] + p2 * wc[10] + p3 * wc[11];
    }
    out[((size_t)(b * 3 + 0)) * 1024 + n] = a0;
    out[((size_t)(b * 3 + 1)) * 1024 + n] = a1;
    out[((size_t)(b * 3 + 2)) * 1024 + n] = a2;
}

extern "C" void kernel_launch(void* const* d_in, const int* in_sizes, int n_in,
                              void* d_out, int out_size) {
    const float* x = (const float*)d_in[0];
    const float* w[10];
    for (int i = 0; i < 10; i++) w[i] = (const float*)d_in[i + 1];

    float *bufA, *bufB, *bufT, *y2, *t2, *gp, *b6, *cb;
    double *dsum, *dss;
    u32* mk;
    cudaGetSymbolAddress((void**)&bufA, g_bufA);
    cudaGetSymbolAddress((void**)&bufB, g_bufB);
    cudaGetSymbolAddress((void**)&bufT, g_bufT);
    cudaGetSymbolAddress((void**)&y2, g_y2);
    cudaGetSymbolAddress((void**)&t2, g_t2);
    cudaGetSymbolAddress((void**)&dsum, g_dsum);
    cudaGetSymbolAddress((void**)&dss, g_dss);
    cudaGetSymbolAddress((void**)&mk, g_maxkey);
    cudaGetSymbolAddress((void**)&gp, g_gpoly);
    cudaGetSymbolAddress((void**)&b6, g_bias6);
    cudaGetSymbolAddress((void**)&cb, g_cbias);

    cudaMemsetAsync(dsum, 0, 10 * 1024 * sizeof(double));
    cudaMemsetAsync(dss, 0, 10 * 1024 * sizeof(double));
    cudaMemsetAsync(mk, 0, 32 * 1024 * sizeof(u32));

    CBArgs cba;
    const int cins[9] = {2, 64, 64, 64, 128, 64, 512, 256, 128};
    const int couts[9] = {64, 64, 64, 128, 1024, 512, 256, 128, 128};
    for (int i = 0; i < 9; i++) { cba.w[i] = w[i]; cba.cin[i] = cins[i]; cba.cout[i] = couts[i]; }
    cbias_all_kernel<<<dim3(4, 9), 256>>>(cba, cb);

    const int PT = 256;  // (b, 128-point) tiles

    // L1: 2 -> 64
    tanh_bn_kernel<<<32 * 2, 256>>>(x, nullptr, nullptr, 2, bufT);
    kan_tc<2, 64, 64, false><<<dim3(PT, 1), 256>>>(bufT, w[0], cb + 0, nullptr, bufA,
                                                   dsum + 0, dss + 0, nullptr);
    // L2: 64 -> 64 (raw out kept as local feature)
    tanh_bn_kernel<<<32 * 64, 256>>>(bufA, dsum + 0, dss + 0, 64, bufT);
    kan_tc<64, 64, 64, false><<<dim3(PT, 1), 256>>>(bufT, w[1], cb + 1024, nullptr, y2,
                                                    dsum + 1024, dss + 1024, nullptr);
    // t2 = tanh(bn(y2)) reused by L3 and L6
    tanh_bn_kernel<<<32 * 64, 256>>>(y2, dsum + 1024, dss + 1024, 64, t2);
    // L3: 64 -> 64
    kan_tc<64, 64, 64, false><<<dim3(PT, 1), 256>>>(t2, w[2], cb + 2048, nullptr, bufA,
                                                    dsum + 2048, dss + 2048, nullptr);
    // L4: 64 -> 128
    tanh_bn_kernel<<<32 * 64, 256>>>(bufA, dsum + 2048, dss + 2048, 64, bufT);
    kan_tc<64, 128, 128, false><<<dim3(PT, 1), 256>>>(bufT, w[3], cb + 3072, nullptr, bufB,
                                                      dsum + 3072, dss + 3072, nullptr);
    // L5: 128 -> 1024 (fused maxpool)
    tanh_bn_kernel<<<32 * 128, 256>>>(bufB, dsum + 3072, dss + 3072, 128, bufT);
    kan_tc<128, 1024, 128, true><<<dim3(PT, 8), 256>>>(bufT, w[4], cb + 4096, nullptr, bufA,
                                                       dsum + 4096, dss + 4096, mk);
    // global feature path
    gpoly_kernel<<<128, 256>>>(mk, dsum + 4096, dss + 4096, gp);
    bias6_kernel<<<dim3(32, 8), 256>>>(gp, w[5] + (size_t)64 * 512 * 4, b6);
    // L6: 64 local channels + gf folded bias -> 512
    kan_tc<64, 512, 128, false><<<dim3(PT, 4), 256>>>(t2, w[5], cb + 5120, b6, bufB,
                                                      dsum + 5120, dss + 5120, nullptr);
    // L7: 512 -> 256
    tanh_bn_kernel<<<32 * 512, 256>>>(bufB, dsum + 5120, dss + 5120, 512, bufT);
    kan_tc<512, 256, 128, false><<<dim3(PT, 2), 256>>>(bufT, w[6], cb + 6144, nullptr, bufA,
                                                       dsum + 6144, dss + 6144, nullptr);
    // L8: 256 -> 128
    tanh_bn_kernel<<<32 * 256, 256>>>(bufA, dsum + 6144, dss + 6144, 256, bufT);
    kan_tc<256, 128, 128, false><<<dim3(PT, 1), 256>>>(bufT, w[7], cb + 7168, nullptr, bufB,
                                                       dsum + 7168, dss + 7168, nullptr);
    // L9: 128 -> 128
    tanh_bn_kernel<<<32 * 128, 256>>>(bufB, dsum + 7168, dss + 7168, 128, bufT);
    kan_tc<128, 128, 128, false><<<dim3(PT, 1), 256>>>(bufT, w[8], cb + 8192, nullptr, bufA,
                                                       dsum + 8192, dss + 8192, nullptr);
    // L10: 128 -> 3 (no BN after)
    tanh_bn_kernel<<<32 * 128, 256>>>(bufA, dsum + 8192, dss + 8192, 128, bufT);
    final_kernel<<<128, 256>>>(bufT, w[9], (float*)d_out);
}

// round 7
// speedup vs baseline: 1.6440x; 1.6440x over previous
#include <cuda_runtime.h>
#include <cuda_bf16.h>
#include <math.h>

// PointNetKAN on GB300, round 6: legacy-path bf16 mma.sync.m16n8k16 (sm_103 base
// target has NO tcgen05 — confirmed by ptxas round 5).
//  - 3-pass hi/lo bf16 compensation: acc += ah*bh + ah*bl + al*bh (fp32 accum)
//  - basis {t,t^2,t^3}: Jacobi transform folded into weights + const bias
//  - ldmatrix.x4 fragments, double-buffered smem, 1 sync per 32-k chunk
//  - fused per-channel BN stats (+max) epilogue; gf broadcast folded to bias

#define NPTS 32768
#define EPSV 1e-5f

typedef unsigned long long u64;
typedef unsigned int u32;

// ---------------- scratch ----------------
__device__ __align__(16) float g_bufA[32u * 1024u * 1024u];
__device__ __align__(16) float g_bufB[32u * 512u * 1024u];
__device__ __align__(16) float g_bufT[32u * 512u * 1024u];
__device__ __align__(16) float g_y2[32u * 64u * 1024u];
__device__ __align__(16) float g_t2[32u * 64u * 1024u];
__device__ double g_dsum[10 * 1024];
__device__ double g_dss[10 * 1024];
__device__ u32 g_maxkey[32 * 1024];
__device__ __align__(16) float g_gpoly[32 * 1024 * 4];
__device__ float g_bias6[32 * 512];
__device__ float g_cbias[9 * 1024];

// ---------------- helpers ----------------
__device__ __forceinline__ u32 fkey(float f) {
    u32 u = __float_as_uint(f);
    return (u & 0x80000000u) ? ~u : (u | 0x80000000u);
}
__device__ __forceinline__ float finv(u32 k) {
    u32 u = (k & 0x80000000u) ? (k ^ 0x80000000u) : ~k;
    return __uint_as_float(u);
}
__device__ __forceinline__ float ftanh(float x) {
    float ax = fminf(fabsf(x), 15.0f);
    float e = __expf(2.0f * ax);
    float t = __fdividef(e - 1.0f, e + 1.0f);
    return copysignf(t, x);
}
__device__ __forceinline__ void jacobi3(float t, float& p1, float& p2, float& p3) {
    p1 = 2.0f * t;
    p2 = 3.75f * t * t - 0.75f;
    p3 = (56.0f / 30.0f) * t * p2 - 0.8f * p1;
}
__device__ __forceinline__ u32 smem_u32(const void* p) {
    u32 a;
    asm("{ .reg .u64 t; cvta.to.shared.u64 t, %1; cvt.u32.u64 %0, t; }" : "=r"(a) : "l"(p));
    return a;
}
__device__ __forceinline__ void ldsm4(u32* r, u32 addr) {
    asm volatile("ldmatrix.sync.aligned.m8n8.x4.shared.b16 {%0,%1,%2,%3}, [%4];"
                 : "=r"(r[0]), "=r"(r[1]), "=r"(r[2]), "=r"(r[3]) : "r"(addr));
}
__device__ __forceinline__ void mma_bf16(float* c, const u32* a, u32 b0, u32 b1) {
    asm volatile(
        "mma.sync.aligned.m16n8k16.row.col.f32.bf16.bf16.f32 "
        "{%0,%1,%2,%3}, {%4,%5,%6,%7}, {%8,%9}, {%0,%1,%2,%3};"
        : "+f"(c[0]), "+f"(c[1]), "+f"(c[2]), "+f"(c[3])
        : "r"(a[0]), "r"(a[1]), "r"(a[2]), "r"(a[3]), "r"(b0), "r"(b1));
}
__device__ __forceinline__ void bf16pair(float v, __nv_bfloat16& h, __nv_bfloat16& l) {
    h = __float2bfloat16(v);
    l = __float2bfloat16(v - __bfloat162float(h));
}

// ---------------- bf16 mma KAN GEMM ----------------
// T: (32, CIN, 1024) tanh'd input. Logical K = 3*CIN over basis {t, t^2, t^3}
// with weights transformed: b(r=0)=2w1-3w3, b(r=1)=3.75w2, b(r=2)=7w3.
// out: (32, COUT, 1024) raw; per-channel stats (+max) via atomics.
template <int CIN, int COUT, int TO, bool DOMAX>
__global__ __launch_bounds__(256) void kan_bf(
    const float* __restrict__ T, const float* __restrict__ w,
    const float* __restrict__ cbias, const float* __restrict__ bias,
    float* __restrict__ out, double* __restrict__ dsum, double* __restrict__ dss,
    u32* __restrict__ maxkey) {
    constexpr int KTOT = 3 * CIN;
    constexpr int KCH = 32;                        // logical k per chunk
    constexpr int NCH = (KTOT + KCH - 1) / KCH;
    constexpr int SA = 40;                         // bf16 row stride (80B, 16B-mult)
    constexpr int ABYTES = 128 * SA * 2;           // one A plane (hi or lo)
    constexpr int BBYTES = TO * SA * 2;
    constexpr int BUFB = 2 * ABYTES + 2 * BBYTES;  // one buffer set
    constexpr int WN = TO / 4;                     // warp n-extent
    constexpr int NT = WN / 8;                     // n8 tiles per warp
    constexpr int NG = NT / 2;                     // n16 ldsm groups per warp
    constexpr int TOSH = (TO == 128) ? 7 : 6;

    extern __shared__ __align__(16) char smem[];
    const u32 sb = smem_u32(smem);
    const int tid = threadIdx.x;
    const int lane = tid & 31, wid = tid >> 5;
    const int g = lane >> 2, tg = lane & 3;
    const int wm = wid & 1, wn = wid >> 1;
    const int b = blockIdx.x >> 3;
    const int pbase = (blockIdx.x & 7) * 128;
    const int o0 = blockIdx.y * TO;

    float acc[4][NT][4];
#pragma unroll
    for (int mt = 0; mt < 4; mt++)
#pragma unroll
        for (int nt = 0; nt < NT; nt++)
#pragma unroll
            for (int r = 0; r < 4; r++) acc[mt][nt][r] = 0.0f;

    // ---- fill one buffer with chunk ch ----
    auto fill = [&](int ch, int buf) {
        char* base = smem + buf * BUFB;
        __nv_bfloat16* Ahi = (__nv_bfloat16*)base;
        __nv_bfloat16* Alo = (__nv_bfloat16*)(base + ABYTES);
        __nv_bfloat16* Bhi = (__nv_bfloat16*)(base + 2 * ABYTES);
        __nv_bfloat16* Blo = (__nv_bfloat16*)(base + 2 * ABYTES + BBYTES);
        const int kbase = ch * KCH;
        // A: powers of t
#pragma unroll 4
        for (int e = tid; e < KCH * 128; e += 256) {
            int p = e & 127, kk = e >> 7;
            int k = kbase + kk;
            float v = 0.0f;
            if (k < KTOT) {
                int c = k / 3, r = k - 3 * c;  // r uniform per warp
                float t = T[(((size_t)(b * CIN + c)) << 10) + pbase + p];
                v = t;
                if (r > 0) v *= t;
                if (r > 1) v *= t;
            }
            __nv_bfloat16 h, l;
            bf16pair(v, h, l);
            Ahi[p * SA + kk] = h;
            Alo[p * SA + kk] = l;
        }
        // B: transformed weights
#pragma unroll 4
        for (int e = tid; e < KCH * TO; e += 256) {
            int o = e & (TO - 1), kk = e >> TOSH;
            int k = kbase + kk;
            float v = 0.0f;
            if (k < KTOT) {
                int c = k / 3, r = k - 3 * c;
                const float4 w4 = *(const float4*)&w[(((size_t)c) * COUT + o0 + o) * 4];
                v = (r == 0) ? (2.0f * w4.y - 3.0f * w4.w)
                             : ((r == 1) ? 3.75f * w4.z : 7.0f * w4.w);
            }
            __nv_bfloat16 h, l;
            bf16pair(v, h, l);
            Bhi[o * SA + kk] = h;
            Blo[o * SA + kk] = l;
        }
    };

    // ldmatrix source addresses (lane-dependent parts precomputed)
    const int a_row = wm * 64 + (lane & 15);
    const int a_col = ((lane >> 4) << 3);
    const int b_row = wn * WN + (lane & 7) + ((lane >> 4) << 3);
    const int b_col = (((lane >> 3) & 1) << 3);

    fill(0, 0);
    __syncthreads();

    for (int ch = 0; ch < NCH; ++ch) {
        const int buf = ch & 1;
        const u32 abase = sb + buf * BUFB;
        const u32 bbase = abase + 2 * ABYTES;
#pragma unroll
        for (int ks = 0; ks < 2; ++ks) {
            u32 ah[16], al[16];
#pragma unroll
            for (int mt = 0; mt < 4; mt++) {
                u32 ad = abase + ((a_row + mt * 16) * SA + ks * 16 + a_col) * 2;
                ldsm4(&ah[4 * mt], ad);
                ldsm4(&al[4 * mt], ad + ABYTES);
            }
            u32 bh[4 * NG], bl[4 * NG];
#pragma unroll
            for (int ng = 0; ng < NG; ng++) {
                u32 bd = bbase + ((b_row + ng * 16) * SA + ks * 16 + b_col) * 2;
                ldsm4(&bh[4 * ng], bd);
                ldsm4(&bl[4 * ng], bd + BBYTES);
            }
#pragma unroll
            for (int mt = 0; mt < 4; mt++)
#pragma unroll
                for (int nt = 0; nt < NT; nt++) {
                    int bi = 4 * (nt >> 1) + 2 * (nt & 1);
                    mma_bf16(acc[mt][nt], &ah[4 * mt], bh[bi], bh[bi + 1]);
                    mma_bf16(acc[mt][nt], &ah[4 * mt], bl[bi], bl[bi + 1]);
                    mma_bf16(acc[mt][nt], &al[4 * mt], bh[bi], bh[bi + 1]);
                }
        }
        if (ch + 1 < NCH) fill(ch + 1, buf ^ 1);
        __syncthreads();
    }

    // ---- epilogue: bias, stores, fused stats (+max) ----
#pragma unroll
    for (int nt = 0; nt < NT; nt++) {
        const int o = o0 + wn * WN + nt * 8 + 2 * tg;
        float add0 = cbias[o] + (bias ? bias[b * COUT + o] : 0.0f);
        float add1 = cbias[o + 1] + (bias ? bias[b * COUT + o + 1] : 0.0f);
        float s0 = 0, ss0 = 0, s1 = 0, ss1 = 0;
        float mx0 = -3.4e38f, mx1 = -3.4e38f;
#pragma unroll
        for (int mt = 0; mt < 4; mt++) {
            int pt = pbase + wm * 64 + mt * 16 + g;
            float v00 = acc[mt][nt][0] + add0, v01 = acc[mt][nt][1] + add1;
            float v10 = acc[mt][nt][2] + add0, v11 = acc[mt][nt][3] + add1;
            float* r0 = out + (((size_t)(b * COUT + o)) << 10) + pt;
            float* r1 = out + (((size_t)(b * COUT + o + 1)) << 10) + pt;
            r0[0] = v00; r0[8] = v10; r1[0] = v01; r1[8] = v11;
            s0 += v00 + v10; ss0 += v00 * v00 + v10 * v10;
            s1 += v01 + v11; ss1 += v01 * v01 + v11 * v11;
            if (DOMAX) { mx0 = fmaxf(mx0, fmaxf(v00, v10)); mx1 = fmaxf(mx1, fmaxf(v01, v11)); }
        }
#pragma unroll
        for (int off = 4; off < 32; off <<= 1) {
            s0 += __shfl_xor_sync(0xffffffffu, s0, off);
            ss0 += __shfl_xor_sync(0xffffffffu, ss0, off);
            s1 += __shfl_xor_sync(0xffffffffu, s1, off);
            ss1 += __shfl_xor_sync(0xffffffffu, ss1, off);
            if (DOMAX) {
                mx0 = fmaxf(mx0, __shfl_xor_sync(0xffffffffu, mx0, off));
                mx1 = fmaxf(mx1, __shfl_xor_sync(0xffffffffu, mx1, off));
            }
        }
        if (lane < 4) {
            atomicAdd(&dsum[o], (double)s0);
            atomicAdd(&dss[o], (double)ss0);
            atomicAdd(&dsum[o + 1], (double)s1);
            atomicAdd(&dss[o + 1], (double)ss1);
            if (DOMAX) {
                atomicMax(&maxkey[b * 1024 + o], fkey(mx0));
                atomicMax(&maxkey[b * 1024 + o + 1], fkey(mx1));
            }
        }
    }
}

// ---------------- BN (from raw accumulators) + fast tanh ----------------
__global__ void tanh_bn_kernel(const float* __restrict__ in, const double* __restrict__ dsum,
                               const double* __restrict__ dss, int C, float* __restrict__ out) {
    int c = blockIdx.x % C;
    float m = 0.0f, r = 1.0f;
    if (dsum) {
        double mm = dsum[c] * (1.0 / NPTS);
        double var = fma(-mm, mm, dss[c] * (1.0 / NPTS));
        m = (float)mm;
        r = rsqrtf((float)var + EPSV);
    }
    const float4* ip = (const float4*)(in + (size_t)blockIdx.x * 1024);
    float4 v = ip[threadIdx.x];
    v.x = ftanh((v.x - m) * r);
    v.y = ftanh((v.y - m) * r);
    v.z = ftanh((v.z - m) * r);
    v.w = ftanh((v.w - m) * r);
    ((float4*)(out + (size_t)blockIdx.x * 1024))[threadIdx.x] = v;
}

// ---------------- per-layer constant biases: sum_c (w0 - 0.75*w2) ----------------
struct CBArgs { const float* w[9]; int cin[9]; int cout[9]; };
__global__ void cbias_all_kernel(CBArgs a, float* __restrict__ cb) {
    int l = blockIdx.y;
    int o = blockIdx.x * 256 + threadIdx.x;
    if (o >= a.cout[l]) return;
    const float* w = a.w[l];
    int CO = a.cout[l];
    float s = 0.0f;
    for (int c = 0; c < a.cin[l]; c++) {
        const float* p = &w[((size_t)c * CO + o) * 4];
        s += p[0] - 0.75f * p[2];
    }
    cb[l * 1024 + o] = s;
}

// ---------------- polys of normalized global feature ----------------
__global__ void gpoly_kernel(const u32* __restrict__ mk, const double* __restrict__ dsum,
                             const double* __restrict__ dss, float* __restrict__ gp) {
    int i = blockIdx.x * 256 + threadIdx.x;
    int c = i & 1023;
    double mm = dsum[c] * (1.0 / NPTS);
    double var = fma(-mm, mm, dss[c] * (1.0 / NPTS));
    float r = rsqrtf((float)var + EPSV);
    float t = ftanh((finv(mk[i]) - (float)mm) * r);
    float p1, p2, p3;
    jacobi3(t, p1, p2, p3);
    ((float4*)gp)[i] = make_float4(1.0f, p1, p2, p3);
}

// ---------------- layer-6 bias from gf rows of w6 (original basis) ----------------
__global__ void bias6_kernel(const float* __restrict__ gp, const float* __restrict__ w6g,
                             float* __restrict__ bias) {
    int b = blockIdx.x;
    int o = blockIdx.y * 64 + (threadIdx.x & 63);
    int js = threadIdx.x >> 6;
    const float4* g4 = (const float4*)(gp + (size_t)b * 4096);
    float acc = 0.0f;
    for (int j = js * 256; j < js * 256 + 256; j++) {
        float4 g = g4[j];
        float4 wv = *(const float4*)&w6g[((size_t)j * 512 + o) * 4];
        acc += g.x * wv.x + g.y * wv.y + g.z * wv.z + g.w * wv.w;
    }
    __shared__ float sh[256];
    sh[threadIdx.x] = acc;
    __syncthreads();
    if (threadIdx.x < 64)
        bias[b * 512 + o] = sh[threadIdx.x] + sh[threadIdx.x + 64] +
                            sh[threadIdx.x + 128] + sh[threadIdx.x + 192];
}

// ---------------- final layer: 128 -> 3 (original basis, fp32) ----------------
__global__ void final_kernel(const float* __restrict__ tin, const float* __restrict__ w,
                             float* __restrict__ out) {
    __shared__ float ws[128 * 12];
    for (int e = threadIdx.x; e < 1536; e += 256) ws[e] = w[e];
    __syncthreads();
    int gidx = blockIdx.x * 256 + threadIdx.x;
    int b = gidx >> 10, n = gidx & 1023;
    float a0 = 0.0f, a1 = 0.0f, a2 = 0.0f;
    for (int c = 0; c < 128; c++) {
        float t = tin[((size_t)(b * 128 + c)) * 1024 + n];
        float p1, p2, p3;
        jacobi3(t, p1, p2, p3);
        const float* wc = &ws[c * 12];
        a0 += wc[0] + p1 * wc[1] + p2 * wc[2] + p3 * wc[3];
        a1 += wc[4] + p1 * wc[5] + p2 * wc[6] + p3 * wc[7];
        a2 += wc[8] + p1 * wc[9] + p2 * wc[10] + p3 * wc[11];
    }
    out[((size_t)(b * 3 + 0)) * 1024 + n] = a0;
    out[((size_t)(b * 3 + 1)) * 1024 + n] = a1;
    out[((size_t)(b * 3 + 2)) * 1024 + n] = a2;
}

extern "C" void kernel_launch(void* const* d_in, const int* in_sizes, int n_in,
                              void* d_out, int out_size) {
    const float* x = (const float*)d_in[0];
    const float* w[10];
    for (int i = 0; i < 10; i++) w[i] = (const float*)d_in[i + 1];

    float *bufA, *bufB, *bufT, *y2, *t2, *gp, *b6, *cb;
    double *dsum, *dss;
    u32* mk;
    cudaGetSymbolAddress((void**)&bufA, g_bufA);
    cudaGetSymbolAddress((void**)&bufB, g_bufB);
    cudaGetSymbolAddress((void**)&bufT, g_bufT);
    cudaGetSymbolAddress((void**)&y2, g_y2);
    cudaGetSymbolAddress((void**)&t2, g_t2);
    cudaGetSymbolAddress((void**)&dsum, g_dsum);
    cudaGetSymbolAddress((void**)&dss, g_dss);
    cudaGetSymbolAddress((void**)&mk, g_maxkey);
    cudaGetSymbolAddress((void**)&gp, g_gpoly);
    cudaGetSymbolAddress((void**)&b6, g_bias6);
    cudaGetSymbolAddress((void**)&cb, g_cbias);

    cudaMemsetAsync(dsum, 0, 10 * 1024 * sizeof(double));
    cudaMemsetAsync(dss, 0, 10 * 1024 * sizeof(double));
    cudaMemsetAsync(mk, 0, 32 * 1024 * sizeof(u32));

    CBArgs cba;
    const int cins[9] = {2, 64, 64, 64, 128, 64, 512, 256, 128};
    const int couts[9] = {64, 64, 64, 128, 1024, 512, 256, 128, 128};
    for (int i = 0; i < 9; i++) { cba.w[i] = w[i]; cba.cin[i] = cins[i]; cba.cout[i] = couts[i]; }
    cbias_all_kernel<<<dim3(4, 9), 256>>>(cba, cb);

    const int SM64 = 61440, SM128 = 81920;
    cudaFuncSetAttribute(kan_bf<2, 64, 64, false>, cudaFuncAttributeMaxDynamicSharedMemorySize, SM64);
    cudaFuncSetAttribute(kan_bf<64, 64, 64, false>, cudaFuncAttributeMaxDynamicSharedMemorySize, SM64);
    cudaFuncSetAttribute(kan_bf<64, 128, 128, false>, cudaFuncAttributeMaxDynamicSharedMemorySize, SM128);
    cudaFuncSetAttribute(kan_bf<128, 1024, 128, true>, cudaFuncAttributeMaxDynamicSharedMemorySize, SM128);
    cudaFuncSetAttribute(kan_bf<64, 512, 128, false>, cudaFuncAttributeMaxDynamicSharedMemorySize, SM128);
    cudaFuncSetAttribute(kan_bf<512, 256, 128, false>, cudaFuncAttributeMaxDynamicSharedMemorySize, SM128);
    cudaFuncSetAttribute(kan_bf<256, 128, 128, false>, cudaFuncAttributeMaxDynamicSharedMemorySize, SM128);
    cudaFuncSetAttribute(kan_bf<128, 128, 128, false>, cudaFuncAttributeMaxDynamicSharedMemorySize, SM128);

    const int GX = 256;  // 32 batches x 8 tiles of 128 points

    // L1: 2 -> 64
    tanh_bn_kernel<<<32 * 2, 256>>>(x, nullptr, nullptr, 2, bufT);
    kan_bf<2, 64, 64, false><<<dim3(GX, 1), 256, SM64>>>(bufT, w[0], cb + 0, nullptr, bufA,
                                                         dsum + 0, dss + 0, nullptr);
    // L2: 64 -> 64 (raw out kept as local feature)
    tanh_bn_kernel<<<32 * 64, 256>>>(bufA, dsum + 0, dss + 0, 64, bufT);
    kan_bf<64, 64, 64, false><<<dim3(GX, 1), 256, SM64>>>(bufT, w[1], cb + 1024, nullptr, y2,
                                                          dsum + 1024, dss + 1024, nullptr);
    // t2 = tanh(bn(y2)) reused by L3 and L6
    tanh_bn_kernel<<<32 * 64, 256>>>(y2, dsum + 1024, dss + 1024, 64, t2);
    // L3: 64 -> 64
    kan_bf<64, 64, 64, false><<<dim3(GX, 1), 256, SM64>>>(t2, w[2], cb + 2048, nullptr, bufA,
                                                          dsum + 2048, dss + 2048, nullptr);
    // L4: 64 -> 128
    tanh_bn_kernel<<<32 * 64, 256>>>(bufA, dsum + 2048, dss + 2048, 64, bufT);
    kan_bf<64, 128, 128, false><<<dim3(GX, 1), 256, SM128>>>(bufT, w[3], cb + 3072, nullptr, bufB,
                                                             dsum + 3072, dss + 3072, nullptr);
    // L5: 128 -> 1024 (fused maxpool)
    tanh_bn_kernel<<<32 * 128, 256>>>(bufB, dsum + 3072, dss + 3072, 128, bufT);
    kan_bf<128, 1024, 128, true><<<dim3(GX, 8), 256, SM128>>>(bufT, w[4], cb + 4096, nullptr, bufA,
                                                              dsum + 4096, dss + 4096, mk);
    // global feature path
    gpoly_kernel<<<128, 256>>>(mk, dsum + 4096, dss + 4096, gp);
    bias6_kernel<<<dim3(32, 8), 256>>>(gp, w[5] + (size_t)64 * 512 * 4, b6);
    // L6: 64 local channels + gf folded bias -> 512
    kan_bf<64, 512, 128, false><<<dim3(GX, 4), 256, SM128>>>(t2, w[5], cb + 5120, b6, bufB,
                                                             dsum + 5120, dss + 5120, nullptr);
    // L7: 512 -> 256
    tanh_bn_kernel<<<32 * 512, 256>>>(bufB, dsum + 5120, dss + 5120, 512, bufT);
    kan_bf<512, 256, 128, false><<<dim3(GX, 2), 256, SM128>>>(bufT, w[6], cb + 6144, nullptr, bufA,
                                                              dsum + 6144, dss + 6144, nullptr);
    // L8: 256 -> 128
    tanh_bn_kernel<<<32 * 256, 256>>>(bufA, dsum + 6144, dss + 6144, 256, bufT);
    kan_bf<256, 128, 128, false><<<dim3(GX, 1), 256, SM128>>>(bufT, w[7], cb + 7168, nullptr, bufB,
                                                              dsum + 7168, dss + 7168, nullptr);
    // L9: 128 -> 128
    tanh_bn_kernel<<<32 * 128, 256>>>(bufB, dsum + 7168, dss + 7168, 128, bufT);
    kan_bf<128, 128, 128, false><<<dim3(GX, 1), 256, SM128>>>(bufT, w[8], cb + 8192, nullptr, bufA,
                                                              dsum + 8192, dss + 8192, nullptr);
    // L10: 128 -> 3 (no BN after)
    tanh_bn_kernel<<<32 * 128, 256>>>(bufA, dsum + 8192, dss + 8192, 128, bufT);
    final_kernel<<<128, 256>>>(bufT, w[9], (float*)d_out);
}

// round 8
// speedup vs baseline: 3.9937x; 2.4293x over previous
#include <cuda_runtime.h>
#include <cuda_bf16.h>
#include <math.h>

// PointNetKAN on GB300, round 8: decoupled transform + lean bf16 mma GEMM.
//  - prep kernel: BN+tanh -> {t,t^2,t^3} -> bf16 hi/lo planes in gmem (k-major)
//  - wprep: weights -> transformed basis bf16 hi/lo, k-major, zero-padded
//  - GEMM: cp.async -> ldmatrix.x4.trans -> 3-pass mma.m16n8k16 (fp32 accum)
//  - fused per-channel BN stats (+max) epilogue; P0 + broadcast-gf folded to biases

#define NPTS 32768
#define EPSV 1e-5f

typedef unsigned long long u64;
typedef unsigned int u32;

// ---------------- scratch ----------------
__device__ __align__(16) float g_bufA[32u * 1024u * 1024u];
__device__ __align__(16) float g_bufB[32u * 512u * 1024u];
__device__ __align__(16) float g_bufT[32u * 128u * 1024u];   // final-layer tanh input
__device__ __align__(16) float g_y2[32u * 64u * 1024u];      // raw L2 out
__device__ __align__(16) __nv_bfloat16 g_Phi[50331648];      // 32*1536*1024
__device__ __align__(16) __nv_bfloat16 g_Plo[50331648];
__device__ __align__(16) __nv_bfloat16 g_P2hi[6291456];      // 32*192*1024 (t2 powers)
__device__ __align__(16) __nv_bfloat16 g_P2lo[6291456];
__device__ __align__(16) __nv_bfloat16 g_Whi[1100000];
__device__ __align__(16) __nv_bfloat16 g_Wlo[1100000];
__device__ double g_dsum[10 * 1024];
__device__ double g_dss[10 * 1024];
__device__ u32 g_maxkey[32 * 1024];
__device__ __align__(16) float g_gpoly[32 * 1024 * 4];
__device__ float g_bias6[32 * 512];
__device__ float g_cbias[9 * 1024];

// ---------------- helpers ----------------
__device__ __forceinline__ u32 fkey(float f) {
    u32 u = __float_as_uint(f);
    return (u & 0x80000000u) ? ~u : (u | 0x80000000u);
}
__device__ __forceinline__ float finv(u32 k) {
    u32 u = (k & 0x80000000u) ? (k ^ 0x80000000u) : ~k;
    return __uint_as_float(u);
}
__device__ __forceinline__ float ftanh(float x) {
    float ax = fminf(fabsf(x), 15.0f);
    float e = __expf(2.0f * ax);
    float t = __fdividef(e - 1.0f, e + 1.0f);
    return copysignf(t, x);
}
__device__ __forceinline__ void jacobi3(float t, float& p1, float& p2, float& p3) {
    p1 = 2.0f * t;
    p2 = 3.75f * t * t - 0.75f;
    p3 = (56.0f / 30.0f) * t * p2 - 0.8f * p1;
}
__device__ __forceinline__ u32 smem_u32(const void* p) {
    u32 a;
    asm("{ .reg .u64 t; cvta.to.shared.u64 t, %1; cvt.u32.u64 %0, t; }" : "=r"(a) : "l"(p));
    return a;
}
__device__ __forceinline__ void cpa16(u32 dst, const void* src) {
    asm volatile("cp.async.cg.shared.global [%0], [%1], 16;" :: "r"(dst), "l"(src) : "memory");
}
__device__ __forceinline__ void ldsm4t(u32* r, u32 addr) {
    asm volatile("ldmatrix.sync.aligned.m8n8.x4.trans.shared.b16 {%0,%1,%2,%3}, [%4];"
                 : "=r"(r[0]), "=r"(r[1]), "=r"(r[2]), "=r"(r[3]) : "r"(addr));
}
__device__ __forceinline__ void mma_bf16(float* c, const u32* a, u32 b0, u32 b1) {
    asm volatile(
        "mma.sync.aligned.m16n8k16.row.col.f32.bf16.bf16.f32 "
        "{%0,%1,%2,%3}, {%4,%5,%6,%7}, {%8,%9}, {%0,%1,%2,%3};"
        : "+f"(c[0]), "+f"(c[1]), "+f"(c[2]), "+f"(c[3])
        : "r"(a[0]), "r"(a[1]), "r"(a[2]), "r"(a[3]), "r"(b0), "r"(b1));
}
__device__ __forceinline__ u32 packbf(float a, float b) {
    __nv_bfloat16 ha = __float2bfloat16(a), hb = __float2bfloat16(b);
    return ((u32)__bfloat16_as_ushort(hb) << 16) | __bfloat16_as_ushort(ha);
}

// ---------------- GEMM: pure cp.async + trans-ldmatrix + mma ----------------
// A planes: Phi/Plo [b][KTOT][1024] bf16 (k-major). B: Whi/Wlo [k][COUT] bf16.
// out: (32, COUT, 1024) fp32 raw; per-channel stats (+max) via atomics.
template <int CIN, int COUT, int TO, bool DOMAX>
__global__ __launch_bounds__(256) void kan_bf(
    const __nv_bfloat16* __restrict__ Phi, const __nv_bfloat16* __restrict__ Plo,
    const __nv_bfloat16* __restrict__ Whi, const __nv_bfloat16* __restrict__ Wlo,
    const float* __restrict__ cbias, const float* __restrict__ bias,
    float* __restrict__ out, double* __restrict__ dsum, double* __restrict__ dss,
    u32* __restrict__ maxkey) {
    constexpr int KTOT = 3 * CIN;
    constexpr int NCH = (KTOT + 31) / 32;
    constexpr int ASTR = 272;                 // bytes per A smem row (128 pts + pad)
    constexpr int BSTR = TO * 2 + 16;         // bytes per B smem row
    constexpr int APL = 32 * ASTR;            // one A plane
    constexpr int BPL = 32 * BSTR;
    constexpr int BUFB = 2 * APL + 2 * BPL;   // one buffer set (Ahi,Alo,Bhi,Blo)
    constexpr int WN = TO / 4;
    constexpr int NT = WN / 8;
    constexpr int NG = NT / 2;

    extern __shared__ __align__(16) char smem[];
    const u32 sb = smem_u32(smem);
    const int tid = threadIdx.x;
    const int lane = tid & 31, wid = tid >> 5;
    const int g = lane >> 2, tg = lane & 3;
    const int wm = wid & 1, wn = wid >> 1;
    const int b = blockIdx.x >> 3;
    const int pbase = (blockIdx.x & 7) * 128;
    const int o0 = blockIdx.y * TO;

    float acc[4][NT][4];
#pragma unroll
    for (int mt = 0; mt < 4; mt++)
#pragma unroll
        for (int nt = 0; nt < NT; nt++)
#pragma unroll
            for (int r = 0; r < 4; r++) acc[mt][nt][r] = 0.0f;

    // zero k-padding rows (L1 only: KTOT=6)
    if (KTOT & 31) {
        for (int e = tid; e < (32 - KTOT) * (ASTR / 4); e += 256) {
            int r = e / (ASTR / 4), wd = e % (ASTR / 4);
            *(u32*)(smem + (KTOT + r) * ASTR + wd * 4) = 0;
            *(u32*)(smem + APL + (KTOT + r) * ASTR + wd * 4) = 0;
        }
    }

    auto load_chunk = [&](int ch, int buf) {
        const int kb = ch << 5;
        const u32 base = sb + buf * BUFB;
#pragma unroll
        for (int j = 0; j < 2; ++j) {  // A: 512 16B-segs per plane
            int s = tid + (j << 8);
            int row = s >> 4, c16 = (s & 15) << 4;
            int k = kb + row;
            if ((KTOT & 31) == 0 || k < KTOT) {
                u32 dst = base + row * ASTR + c16;
                size_t gel = (((size_t)(b * KTOT + k)) << 10) + pbase;
                cpa16(dst, (const char*)(Phi + gel) + c16);
                cpa16(dst + APL, (const char*)(Plo + gel) + c16);
            }
        }
        constexpr int BS = 32 * (TO / 8);
#pragma unroll
        for (int j = 0; j < BS / 256; ++j) {
            int s = tid + (j << 8);
            int row = s / (TO / 8), c16 = (s % (TO / 8)) << 4;
            int k = kb + row;
            u32 dst = base + 2 * APL + row * BSTR + c16;
            size_t gel = (size_t)k * COUT + o0;
            cpa16(dst, (const char*)(Whi + gel) + c16);
            cpa16(dst + BPL, (const char*)(Wlo + gel) + c16);
        }
    };

    // lane-dependent ldmatrix offsets
    const u32 a_lofs = ((lane & 7) + ((lane >> 4) << 3)) * ASTR + (((lane >> 3) & 1) << 4);
    const u32 b_lofs = ((lane & 7) + (((lane >> 3) & 1) << 3)) * BSTR + ((lane >> 4) << 4);

    load_chunk(0, 0);
    asm volatile("cp.async.commit_group;" ::: "memory");

    for (int ch = 0; ch < NCH; ++ch) {
        const int buf = ch & 1;
        if (ch + 1 < NCH) {
            load_chunk(ch + 1, buf ^ 1);
            asm volatile("cp.async.commit_group;" ::: "memory");
            asm volatile("cp.async.wait_group 1;" ::: "memory");
        } else {
            asm volatile("cp.async.wait_group 0;" ::: "memory");
        }
        __syncthreads();

        const u32 ab = sb + buf * BUFB;
        const u32 bb = ab + 2 * APL;
#pragma unroll
        for (int ks = 0; ks < 2; ++ks) {
            u32 ah[16], al[16];
#pragma unroll
            for (int mt = 0; mt < 4; mt++) {
                u32 ad = ab + ks * (16 * ASTR) + a_lofs + (wm * 64 + mt * 16) * 2;
                ldsm4t(&ah[4 * mt], ad);
                ldsm4t(&al[4 * mt], ad + APL);
            }
            u32 bh[4 * NG], bl[4 * NG];
#pragma unroll
            for (int ng = 0; ng < NG; ng++) {
                u32 bd = bb + ks * (16 * BSTR) + b_lofs + (wn * WN + ng * 16) * 2;
                ldsm4t(&bh[4 * ng], bd);
                ldsm4t(&bl[4 * ng], bd + BPL);
            }
#pragma unroll
            for (int mt = 0; mt < 4; mt++)
#pragma unroll
                for (int nt = 0; nt < NT; nt++) {
                    int bi = 4 * (nt >> 1) + 2 * (nt & 1);
                    mma_bf16(acc[mt][nt], &ah[4 * mt], bh[bi], bh[bi + 1]);
                    mma_bf16(acc[mt][nt], &ah[4 * mt], bl[bi], bl[bi + 1]);
                    mma_bf16(acc[mt][nt], &al[4 * mt], bh[bi], bh[bi + 1]);
                }
        }
        if (ch + 1 < NCH) __syncthreads();
    }

    // ---- epilogue: bias, stores, fused stats (+max) ----
#pragma unroll
    for (int nt = 0; nt < NT; nt++) {
        const int o = o0 + wn * WN + nt * 8 + 2 * tg;
        float add0 = cbias[o] + (bias ? bias[b * COUT + o] : 0.0f);
        float add1 = cbias[o + 1] + (bias ? bias[b * COUT + o + 1] : 0.0f);
        float s0 = 0, ss0 = 0, s1 = 0, ss1 = 0;
        float mx0 = -3.4e38f, mx1 = -3.4e38f;
#pragma unroll
        for (int mt = 0; mt < 4; mt++) {
            int pt = pbase + wm * 64 + mt * 16 + g;
            float v00 = acc[mt][nt][0] + add0, v01 = acc[mt][nt][1] + add1;
            float v10 = acc[mt][nt][2] + add0, v11 = acc[mt][nt][3] + add1;
            float* r0 = out + (((size_t)(b * COUT + o)) << 10) + pt;
            float* r1 = out + (((size_t)(b * COUT + o + 1)) << 10) + pt;
            r0[0] = v00; r0[8] = v10; r1[0] = v01; r1[8] = v11;
            s0 += v00 + v10; ss0 += v00 * v00 + v10 * v10;
            s1 += v01 + v11; ss1 += v01 * v01 + v11 * v11;
            if (DOMAX) { mx0 = fmaxf(mx0, fmaxf(v00, v10)); mx1 = fmaxf(mx1, fmaxf(v01, v11)); }
        }
#pragma unroll
        for (int off = 4; off < 32; off <<= 1) {
            s0 += __shfl_xor_sync(0xffffffffu, s0, off);
            ss0 += __shfl_xor_sync(0xffffffffu, ss0, off);
            s1 += __shfl_xor_sync(0xffffffffu, s1, off);
            ss1 += __shfl_xor_sync(0xffffffffu, ss1, off);
            if (DOMAX) {
                mx0 = fmaxf(mx0, __shfl_xor_sync(0xffffffffu, mx0, off));
                mx1 = fmaxf(mx1, __shfl_xor_sync(0xffffffffu, mx1, off));
            }
        }
        if (lane < 4) {
            atomicAdd(&dsum[o], (double)s0);
            atomicAdd(&dss[o], (double)ss0);
            atomicAdd(&dsum[o + 1], (double)s1);
            atomicAdd(&dss[o + 1], (double)ss1);
            if (DOMAX) {
                atomicMax(&maxkey[b * 1024 + o], fkey(mx0));
                atomicMax(&maxkey[b * 1024 + o + 1], fkey(mx1));
            }
        }
    }
}

// ---------------- prep: BN + tanh -> power planes (bf16 hi/lo, k-major) ----------------
template <bool TOUT>
__global__ void prep_kernel(const float* __restrict__ in, const double* __restrict__ dsum,
                            const double* __restrict__ dss, int C,
                            __nv_bfloat16* __restrict__ Phi, __nv_bfloat16* __restrict__ Plo,
                            float* __restrict__ Tout) {
    int bi = blockIdx.x;
    int c = bi % C, b = bi / C;
    float m = 0.0f, r = 1.0f;
    if (dsum) {
        double mm = dsum[c] * (1.0 / NPTS);
        double var = fma(-mm, mm, dss[c] * (1.0 / NPTS));
        m = (float)mm;
        r = rsqrtf((float)var + EPSV);
    }
    int i = threadIdx.x;
    float4 v = ((const float4*)(in + ((size_t)bi << 10)))[i];
    float t0 = ftanh((v.x - m) * r), t1 = ftanh((v.y - m) * r);
    float t2 = ftanh((v.z - m) * r), t3 = ftanh((v.w - m) * r);
    if (TOUT) ((float4*)(Tout + ((size_t)bi << 10)))[i] = make_float4(t0, t1, t2, t3);
    size_t row = ((size_t)(b * 3 * C + 3 * c)) << 10;
    float p0 = t0, p1 = t1, p2 = t2, p3 = t3;
#pragma unroll
    for (int rr = 0; rr < 3; ++rr) {
        if (rr) { p0 *= t0; p1 *= t1; p2 *= t2; p3 *= t3; }
        __nv_bfloat16 h0 = __float2bfloat16(p0), h1 = __float2bfloat16(p1);
        __nv_bfloat16 h2 = __float2bfloat16(p2), h3 = __float2bfloat16(p3);
        uint2 hv, lv;
        hv.x = ((u32)__bfloat16_as_ushort(h1) << 16) | __bfloat16_as_ushort(h0);
        hv.y = ((u32)__bfloat16_as_ushort(h3) << 16) | __bfloat16_as_ushort(h2);
        lv.x = packbf(p0 - __bfloat162float(h0), p1 - __bfloat162float(h1));
        lv.y = packbf(p2 - __bfloat162float(h2), p3 - __bfloat162float(h3));
        ((uint2*)(Phi + row + ((size_t)rr << 10)))[i] = hv;
        ((uint2*)(Plo + row + ((size_t)rr << 10)))[i] = lv;
    }
}

// ---------------- weight prep: transformed basis, k-major, zero-padded ----------------
struct WPArgs { const float* w[9]; int cin[9]; int cout[9]; long long off[9]; };
__global__ void wprep_kernel(WPArgs a, __nv_bfloat16* __restrict__ Whi,
                             __nv_bfloat16* __restrict__ Wlo) {
    int l = blockIdx.y;
    int CO = a.cout[l];
    int KP = ((3 * a.cin[l] + 31) / 32) * 32;
    int total = KP * CO;
    int idx = blockIdx.x * 256 + threadIdx.x;
    if (idx >= total) return;
    int k = idx / CO, o = idx - k * CO;
    float v = 0.0f;
    if (k < 3 * a.cin[l]) {
        int c = k / 3, r = k - 3 * c;
        const float* p = a.w[l] + (((size_t)c * CO + o) << 2);
        v = (r == 0) ? (2.0f * p[1] - 3.0f * p[3]) : ((r == 1) ? 3.75f * p[2] : 7.0f * p[3]);
    }
    __nv_bfloat16 h = __float2bfloat16(v);
    Whi[a.off[l] + idx] = h;
    Wlo[a.off[l] + idx] = __float2bfloat16(v - __bfloat162float(h));
}

// ---------------- per-layer constant biases: sum_c (w0 - 0.75*w2) ----------------
struct CBArgs { const float* w[9]; int cin[9]; int cout[9]; };
__global__ void cbias_all_kernel(CBArgs a, float* __restrict__ cb) {
    int l = blockIdx.y;
    int o = blockIdx.x * 256 + threadIdx.x;
    if (o >= a.cout[l]) return;
    const float* w = a.w[l];
    int CO = a.cout[l];
    float s = 0.0f;
    for (int c = 0; c < a.cin[l]; c++) {
        const float* p = &w[((size_t)c * CO + o) * 4];
        s += p[0] - 0.75f * p[2];
    }
    cb[l * 1024 + o] = s;
}

// ---------------- BN + tanh (fp32 out; final-layer input) ----------------
__global__ void tanh_bn_kernel(const float* __restrict__ in, const double* __restrict__ dsum,
                               const double* __restrict__ dss, int C, float* __restrict__ out) {
    int c = blockIdx.x % C;
    double mm = dsum[c] * (1.0 / NPTS);
    double var = fma(-mm, mm, dss[c] * (1.0 / NPTS));
    float m = (float)mm;
    float r = rsqrtf((float)var + EPSV);
    const float4* ip = (const float4*)(in + (size_t)blockIdx.x * 1024);
    float4 v = ip[threadIdx.x];
    v.x = ftanh((v.x - m) * r);
    v.y = ftanh((v.y - m) * r);
    v.z = ftanh((v.z - m) * r);
    v.w = ftanh((v.w - m) * r);
    ((float4*)(out + (size_t)blockIdx.x * 1024))[threadIdx.x] = v;
}

// ---------------- polys of normalized global feature ----------------
__global__ void gpoly_kernel(const u32* __restrict__ mk, const double* __restrict__ dsum,
                             const double* __restrict__ dss, float* __restrict__ gp) {
    int i = blockIdx.x * 256 + threadIdx.x;
    int c = i & 1023;
    double mm = dsum[c] * (1.0 / NPTS);
    double var = fma(-mm, mm, dss[c] * (1.0 / NPTS));
    float r = rsqrtf((float)var + EPSV);
    float t = ftanh((finv(mk[i]) - (float)mm) * r);
    float p1, p2, p3;
    jacobi3(t, p1, p2, p3);
    ((float4*)gp)[i] = make_float4(1.0f, p1, p2, p3);
}

// ---------------- layer-6 bias from gf rows of w6 (original basis) ----------------
__global__ void bias6_kernel(const float* __restrict__ gp, const float* __restrict__ w6g,
                             float* __restrict__ bias) {
    int b = blockIdx.x;
    int o = blockIdx.y * 64 + (threadIdx.x & 63);
    int js = threadIdx.x >> 6;
    const float4* g4 = (const float4*)(gp + (size_t)b * 4096);
    float acc = 0.0f;
    for (int j = js * 256; j < js * 256 + 256; j++) {
        float4 g = g4[j];
        float4 wv = *(const float4*)&w6g[((size_t)j * 512 + o) * 4];
        acc += g.x * wv.x + g.y * wv.y + g.z * wv.z + g.w * wv.w;
    }
    __shared__ float sh[256];
    sh[threadIdx.x] = acc;
    __syncthreads();
    if (threadIdx.x < 64)
        bias[b * 512 + o] = sh[threadIdx.x] + sh[threadIdx.x + 64] +
                            sh[threadIdx.x + 128] + sh[threadIdx.x + 192];
}

// ---------------- final layer: 128 -> 3 (fp32) ----------------
__global__ void final_kernel(const float* __restrict__ tin, const float* __restrict__ w,
                             float* __restrict__ out) {
    __shared__ float ws[128 * 12];
    for (int e = threadIdx.x; e < 1536; e += 256) ws[e] = w[e];
    __syncthreads();
    int gidx = blockIdx.x * 256 + threadIdx.x;
    int b = gidx >> 10, n = gidx & 1023;
    float a0 = 0.0f, a1 = 0.0f, a2 = 0.0f;
    for (int c = 0; c < 128; c++) {
        float t = tin[((size_t)(b * 128 + c)) * 1024 + n];
        float p1, p2, p3;
        jacobi3(t, p1, p2, p3);
        const float* wc = &ws[c * 12];
        a0 += wc[0] + p1 * wc[1] + p2 * wc[2] + p3 * wc[3];
        a1 += wc[4] + p1 * wc[5] + p2 * wc[6] + p3 * wc[7];
        a2 += wc[8] + p1 * wc[9] + p2 * wc[10] + p3 * wc[11];
    }
    out[((size_t)(b * 3 + 0)) * 1024 + n] = a0;
    out[((size_t)(b * 3 + 1)) * 1024 + n] = a1;
    out[((size_t)(b * 3 + 2)) * 1024 + n] = a2;
}

extern "C" void kernel_launch(void* const* d_in, const int* in_sizes, int n_in,
                              void* d_out, int out_size) {
    const float* x = (const float*)d_in[0];
    const float* w[10];
    for (int i = 0; i < 10; i++) w[i] = (const float*)d_in[i + 1];

    float *bufA, *bufB, *bufT, *y2, *gp, *b6, *cb;
    __nv_bfloat16 *Phi, *Plo, *P2hi, *P2lo, *Whi, *Wlo;
    double *dsum, *dss;
    u32* mk;
    cudaGetSymbolAddress((void**)&bufA, g_bufA);
    cudaGetSymbolAddress((void**)&bufB, g_bufB);
    cudaGetSymbolAddress((void**)&bufT, g_bufT);
    cudaGetSymbolAddress((void**)&y2, g_y2);
    cudaGetSymbolAddress((void**)&Phi, g_Phi);
    cudaGetSymbolAddress((void**)&Plo, g_Plo);
    cudaGetSymbolAddress((void**)&P2hi, g_P2hi);
    cudaGetSymbolAddress((void**)&P2lo, g_P2lo);
    cudaGetSymbolAddress((void**)&Whi, g_Whi);
    cudaGetSymbolAddress((void**)&Wlo, g_Wlo);
    cudaGetSymbolAddress((void**)&dsum, g_dsum);
    cudaGetSymbolAddress((void**)&dss, g_dss);
    cudaGetSymbolAddress((void**)&mk, g_maxkey);
    cudaGetSymbolAddress((void**)&gp, g_gpoly);
    cudaGetSymbolAddress((void**)&b6, g_bias6);
    cudaGetSymbolAddress((void**)&cb, g_cbias);

    cudaMemsetAsync(dsum, 0, 10 * 1024 * sizeof(double));
    cudaMemsetAsync(dss, 0, 10 * 1024 * sizeof(double));
    cudaMemsetAsync(mk, 0, 32 * 1024 * sizeof(u32));

    const int cins[9] = {2, 64, 64, 64, 128, 64, 512, 256, 128};
    const int couts[9] = {64, 64, 64, 128, 1024, 512, 256, 128, 128};
    // k-padded weight offsets (elements)
    long long offs[9];
    long long acc = 0;
    for (int i = 0; i < 9; i++) {
        offs[i] = acc;
        long long kp = ((3 * cins[i] + 31) / 32) * 32;
        acc += kp * couts[i];
    }

    CBArgs cba;
    WPArgs wpa;
    for (int i = 0; i < 9; i++) {
        cba.w[i] = w[i]; cba.cin[i] = cins[i]; cba.cout[i] = couts[i];
        wpa.w[i] = w[i]; wpa.cin[i] = cins[i]; wpa.cout[i] = couts[i]; wpa.off[i] = offs[i];
    }
    cbias_all_kernel<<<dim3(4, 9), 256>>>(cba, cb);
    wprep_kernel<<<dim3(1536, 9), 256>>>(wpa, Whi, Wlo);

    const int SM64 = 53248, SM128 = 69632;
    cudaFuncSetAttribute(kan_bf<2, 64, 64, false>, cudaFuncAttributeMaxDynamicSharedMemorySize, SM64);
    cudaFuncSetAttribute(kan_bf<64, 64, 64, false>, cudaFuncAttributeMaxDynamicSharedMemorySize, SM64);
    cudaFuncSetAttribute(kan_bf<64, 128, 128, false>, cudaFuncAttributeMaxDynamicSharedMemorySize, SM128);
    cudaFuncSetAttribute(kan_bf<128, 1024, 128, true>, cudaFuncAttributeMaxDynamicSharedMemorySize, SM128);
    cudaFuncSetAttribute(kan_bf<64, 512, 128, false>, cudaFuncAttributeMaxDynamicSharedMemorySize, SM128);
    cudaFuncSetAttribute(kan_bf<512, 256, 128, false>, cudaFuncAttributeMaxDynamicSharedMemorySize, SM128);
    cudaFuncSetAttribute(kan_bf<256, 128, 128, false>, cudaFuncAttributeMaxDynamicSharedMemorySize, SM128);
    cudaFuncSetAttribute(kan_bf<128, 128, 128, false>, cudaFuncAttributeMaxDynamicSharedMemorySize, SM128);

    const int GX = 256;  // 32 batches x 8 tiles of 128 points

    // L1: 2 -> 64
    prep_kernel<false><<<32 * 2, 256>>>(x, nullptr, nullptr, 2, Phi, Plo, nullptr);
    kan_bf<2, 64, 64, false><<<dim3(GX, 1), 256, SM64>>>(Phi, Plo, Whi + offs[0], Wlo + offs[0],
                                                         cb + 0, nullptr, bufA, dsum + 0, dss + 0, nullptr);
    // L2: 64 -> 64 (raw out kept as local feature)
    prep_kernel<false><<<32 * 64, 256>>>(bufA, dsum + 0, dss + 0, 64, Phi, Plo, nullptr);
    kan_bf<64, 64, 64, false><<<dim3(GX, 1), 256, SM64>>>(Phi, Plo, Whi + offs[1], Wlo + offs[1],
                                                          cb + 1024, nullptr, y2, dsum + 1024, dss + 1024, nullptr);
    // t2 power planes (reused by L3 and L6)
    prep_kernel<false><<<32 * 64, 256>>>(y2, dsum + 1024, dss + 1024, 64, P2hi, P2lo, nullptr);
    // L3: 64 -> 64
    kan_bf<64, 64, 64, false><<<dim3(GX, 1), 256, SM64>>>(P2hi, P2lo, Whi + offs[2], Wlo + offs[2],
                                                          cb + 2048, nullptr, bufA, dsum + 2048, dss + 2048, nullptr);
    // L4: 64 -> 128
    prep_kernel<false><<<32 * 64, 256>>>(bufA, dsum + 2048, dss + 2048, 64, Phi, Plo, nullptr);
    kan_bf<64, 128, 128, false><<<dim3(GX, 1), 256, SM128>>>(Phi, Plo, Whi + offs[3], Wlo + offs[3],
                                                             cb + 3072, nullptr, bufB, dsum + 3072, dss + 3072, nullptr);
    // L5: 128 -> 1024 (fused maxpool)
    prep_kernel<false><<<32 * 128, 256>>>(bufB, dsum + 3072, dss + 3072, 128, Phi, Plo, nullptr);
    kan_bf<128, 1024, 128, true><<<dim3(GX, 8), 256, SM128>>>(Phi, Plo, Whi + offs[4], Wlo + offs[4],
                                                              cb + 4096, nullptr, bufA, dsum + 4096, dss + 4096, mk);
    // global feature path
    gpoly_kernel<<<128, 256>>>(mk, dsum + 4096, dss + 4096, gp);
    bias6_kernel<<<dim3(32, 8), 256>>>(gp, w[5] + (size_t)64 * 512 * 4, b6);
    // L6: 64 local channels + gf folded bias -> 512
    kan_bf<64, 512, 128, false><<<dim3(GX, 4), 256, SM128>>>(P2hi, P2lo, Whi + offs[5], Wlo + offs[5],
                                                             cb + 5120, b6, bufB, dsum + 5120, dss + 5120, nullptr);
    // L7: 512 -> 256
    prep_kernel<false><<<32 * 512, 256>>>(bufB, dsum + 5120, dss + 5120, 512, Phi, Plo, nullptr);
    kan_bf<512, 256, 128, false><<<dim3(GX, 2), 256, SM128>>>(Phi, Plo, Whi + offs[6], Wlo + offs[6],
                                                              cb + 6144, nullptr, bufA, dsum + 6144, dss + 6144, nullptr);
    // L8: 256 -> 128
    prep_kernel<false><<<32 * 256, 256>>>(bufA, dsum + 6144, dss + 6144, 256, Phi, Plo, nullptr);
    kan_bf<256, 128, 128, false><<<dim3(GX, 1), 256, SM128>>>(Phi, Plo, Whi + offs[7], Wlo + offs[7],
                                                              cb + 7168, nullptr, bufB, dsum + 7168, dss + 7168, nullptr);
    // L9: 128 -> 128
    prep_kernel<false><<<32 * 128, 256>>>(bufB, dsum + 7168, dss + 7168, 128, Phi, Plo, nullptr);
    kan_bf<128, 128, 128, false><<<dim3(GX, 1), 256, SM128>>>(Phi, Plo, Whi + offs[8], Wlo + offs[8],
                                                              cb + 8192, nullptr, bufA, dsum + 8192, dss + 8192, nullptr);
    // L10: 128 -> 3 (no BN after)
    tanh_bn_kernel<<<32 * 128, 256>>>(bufA, dsum + 8192, dss + 8192, 128, bufT);
    final_kernel<<<128, 256>>>(bufT, w[9], (float*)d_out);
}